// round 11
// baseline (speedup 1.0000x reference)
#include <cuda_runtime.h>

#define N_NODES 100000
#define N_EDGES 1600000
#define F_IN 32
#define HID 16

#define NB_ZERO   1563   // ceil(400000 float4 / 256)
#define NB_PRE    391    // ceil(100000 / 256)
#define NB_EDGE   25000  // 1.6M edges * 4 threads / 256

// Scratch (no allocations allowed in kernel_launch)
__device__ __align__(16) float g_deg [N_NODES];
__device__ __align__(16) float g_xt  [N_NODES * HID];   // x @ W1_l.T
__device__ __align__(16) float g_xr1 [N_NODES * HID];   // x @ W1_r.T
__device__ __align__(16) float g_sum1[N_NODES * HID];   // fp32 accumulators L1
__device__ __align__(16) float g_h   [N_NODES * HID];   // relu(layer1)
__device__ __align__(16) float g_sumh[N_NODES * HID];   // fp32 accumulators L2

__device__ __forceinline__ void red_add_v4(float* addr, float4 v) {
    asm volatile("red.global.add.v4.f32 [%0], {%1,%2,%3,%4};"
                 :: "l"(addr), "f"(v.x), "f"(v.y), "f"(v.z), "f"(v.w)
                 : "memory");
}

// Per-node matvec: out[n,0:16] = x[n,:] @ W.T   (weights in smem, LDS.128)
__device__ __forceinline__ void matvec16(const float* __restrict__ x,
                                         const float* Wsh, int n, float* gdst) {
    float xr[F_IN];
    const float4* xp = reinterpret_cast<const float4*>(x + (size_t)n * F_IN);
#pragma unroll
    for (int g = 0; g < F_IN / 4; g++) {
        float4 v = __ldg(xp + g);
        xr[4*g+0] = v.x; xr[4*g+1] = v.y; xr[4*g+2] = v.z; xr[4*g+3] = v.w;
    }
    const float4* ws4 = reinterpret_cast<const float4*>(Wsh);
    float4* dp = reinterpret_cast<float4*>(gdst + (size_t)n * HID);
#pragma unroll
    for (int og = 0; og < HID / 4; og++) {
        float4 r;
        float* rp = &r.x;
#pragma unroll
        for (int oo = 0; oo < 4; oo++) {
            int o = og * 4 + oo;
            float acc = 0.0f;
#pragma unroll
            for (int kg = 0; kg < F_IN / 4; kg++) {
                float4 w = ws4[o * (F_IN / 4) + kg];
                acc += xr[4*kg+0] * w.x + xr[4*kg+1] * w.y
                     + xr[4*kg+2] * w.z + xr[4*kg+3] * w.w;
            }
            rp[oo] = acc;
        }
        dp[og] = r;
    }
}

// ---------------------------------------------------------------------------
// K1: blocks [0,NB_ZERO): zero sum1 + deg.  blocks [NB_ZERO,+NB_PRE): xt=x@W1l.T
// ---------------------------------------------------------------------------
__global__ void __launch_bounds__(256) k1(const float* __restrict__ x,
                                          const float* __restrict__ W1l) {
    int b = blockIdx.x;
    if (b < NB_ZERO) {
        int t = b * 256 + threadIdx.x;
        float4 z = make_float4(0.f, 0.f, 0.f, 0.f);
        if (t < N_NODES * HID / 4) reinterpret_cast<float4*>(g_sum1)[t] = z;
        if (t < N_NODES / 4)       reinterpret_cast<float4*>(g_deg)[t]  = z;
        return;
    }
    __shared__ float Ws[HID * F_IN];
    for (int i = threadIdx.x; i < HID * F_IN; i += blockDim.x) Ws[i] = W1l[i];
    __syncthreads();
    int n = (b - NB_ZERO) * 256 + threadIdx.x;
    if (n >= N_NODES) return;
    matvec16(x, Ws, n, g_xt);
}

// ---------------------------------------------------------------------------
// K2: blocks [0,NB_EDGE): scatter1 (sum1[dst]+=xt[src], deg[dst]+=1; 4 thr/edge)
//     blocks [NB_EDGE,+NB_PRE): xr1 = x@W1r.T
//     blocks [NB_EDGE+NB_PRE,+NB_ZERO): zero sumh
// ---------------------------------------------------------------------------
__global__ void __launch_bounds__(256) k2(const int* __restrict__ ei,
                                          const float* __restrict__ x,
                                          const float* __restrict__ W1r) {
    int b = blockIdx.x;
    if (b < NB_EDGE) {
        unsigned t = b * 256 + threadIdx.x;
        unsigned e = t >> 2;
        unsigned q = t & 3;
        int s = __ldg(ei + e);
        int d = __ldg(ei + N_EDGES + e);
        if (q == 0) atomicAdd(&g_deg[d], 1.0f);
        float4 v = *reinterpret_cast<const float4*>(g_xt + (size_t)s * HID + q * 4);
        red_add_v4(g_sum1 + (size_t)d * HID + q * 4, v);
        return;
    }
    if (b < NB_EDGE + NB_PRE) {
        __shared__ float Ws[HID * F_IN];
        for (int i = threadIdx.x; i < HID * F_IN; i += blockDim.x) Ws[i] = W1r[i];
        __syncthreads();
        int n = (b - NB_EDGE) * 256 + threadIdx.x;
        if (n >= N_NODES) return;
        matvec16(x, Ws, n, g_xr1);
        return;
    }
    int t = (b - NB_EDGE - NB_PRE) * 256 + threadIdx.x;
    if (t < N_NODES * HID / 4) {
        reinterpret_cast<float4*>(g_sumh)[t] = make_float4(0.f, 0.f, 0.f, 0.f);
    }
}

// ---------------------------------------------------------------------------
// K3: h = relu(sum1/max(deg,1) + b1 + xr1)   — elementwise, 4 thr/node
// ---------------------------------------------------------------------------
__global__ void k3_node1(const float* __restrict__ b1) {
    unsigned t = blockIdx.x * blockDim.x + threadIdx.x;
    unsigned n = t >> 2;
    unsigned q = t & 3;
    if (n >= N_NODES) return;

    float inv = 1.0f / fmaxf(__ldg(&g_deg[n]), 1.0f);
    float4 s = *reinterpret_cast<const float4*>(g_sum1 + (size_t)n * HID + q * 4);
    float4 r = *reinterpret_cast<const float4*>(g_xr1  + (size_t)n * HID + q * 4);
    float4 b = __ldg(reinterpret_cast<const float4*>(b1) + q);

    float4 o;
    o.x = fmaxf(s.x * inv + b.x + r.x, 0.0f);
    o.y = fmaxf(s.y * inv + b.y + r.y, 0.0f);
    o.z = fmaxf(s.z * inv + b.z + r.z, 0.0f);
    o.w = fmaxf(s.w * inv + b.w + r.w, 0.0f);
    *reinterpret_cast<float4*>(g_h + (size_t)n * HID + q * 4) = o;
}

// ---------------------------------------------------------------------------
// K4: scatter2: sumh[dst] += h[src]  (4 threads/edge)
// ---------------------------------------------------------------------------
__global__ void k4_scatter2(const int* __restrict__ ei) {
    unsigned t = blockIdx.x * blockDim.x + threadIdx.x;
    unsigned e = t >> 2;
    unsigned q = t & 3;
    if (e >= N_EDGES) return;
    int s = __ldg(ei + e);
    int d = __ldg(ei + N_EDGES + e);

    float4 v = *reinterpret_cast<const float4*>(g_h + (size_t)s * HID + q * 4);
    red_add_v4(g_sumh + (size_t)d * HID + q * 4, v);
}

// ---------------------------------------------------------------------------
// K5: out = (sumh*inv)@W2_l.T + b2 + h@W2_r.T   (1 thr/node, LDS.128 weights)
// ---------------------------------------------------------------------------
__global__ void __launch_bounds__(256) k5_node2(float* __restrict__ out,
                        const float* __restrict__ W2l,
                        const float* __restrict__ b2,
                        const float* __restrict__ W2r) {
    __shared__ float Wl[F_IN * HID];
    __shared__ float Wr[F_IN * HID];
    __shared__ float bs[F_IN];
    for (int i = threadIdx.x; i < F_IN * HID; i += blockDim.x) {
        Wl[i] = W2l[i];
        Wr[i] = W2r[i];
    }
    if (threadIdx.x < F_IN) bs[threadIdx.x] = b2[threadIdx.x];
    __syncthreads();

    int n = blockIdx.x * blockDim.x + threadIdx.x;
    if (n >= N_NODES) return;

    float inv = 1.0f / fmaxf(g_deg[n], 1.0f);

    float hr[HID], ar[HID];
    const float4* hp = reinterpret_cast<const float4*>(g_h    + (size_t)n * HID);
    const float4* ap = reinterpret_cast<const float4*>(g_sumh + (size_t)n * HID);
#pragma unroll
    for (int g = 0; g < HID / 4; g++) {
        float4 v = hp[g];
        hr[4*g+0] = v.x; hr[4*g+1] = v.y; hr[4*g+2] = v.z; hr[4*g+3] = v.w;
        float4 a = ap[g];
        ar[4*g+0] = a.x * inv; ar[4*g+1] = a.y * inv;
        ar[4*g+2] = a.z * inv; ar[4*g+3] = a.w * inv;
    }

    const float4* Wl4 = reinterpret_cast<const float4*>(Wl);
    const float4* Wr4 = reinterpret_cast<const float4*>(Wr);

    float4* op = reinterpret_cast<float4*>(out + (size_t)n * F_IN);
#pragma unroll
    for (int fg = 0; fg < F_IN / 4; fg++) {
        float4 r;
        float* rp = &r.x;
#pragma unroll
        for (int ff = 0; ff < 4; ff++) {
            int f = fg * 4 + ff;
            float acc = bs[f];
#pragma unroll
            for (int kg = 0; kg < HID / 4; kg++) {
                float4 wl = Wl4[f * (HID / 4) + kg];
                float4 wr = Wr4[f * (HID / 4) + kg];
                acc += ar[4*kg+0] * wl.x + ar[4*kg+1] * wl.y
                     + ar[4*kg+2] * wl.z + ar[4*kg+3] * wl.w
                     + hr[4*kg+0] * wr.x + hr[4*kg+1] * wr.y
                     + hr[4*kg+2] * wr.z + hr[4*kg+3] * wr.w;
            }
            rp[ff] = acc;
        }
        op[fg] = r;
    }
}

// ---------------------------------------------------------------------------
extern "C" void kernel_launch(void* const* d_in, const int* in_sizes, int n_in,
                              void* d_out, int out_size) {
    const float* x   = (const float*)d_in[0];
    const int*   ei  = (const int*)d_in[1];   // [1,2,E], int32 (JAX x64 off)
    const float* W1l = (const float*)d_in[2];
    const float* b1  = (const float*)d_in[3];
    const float* W1r = (const float*)d_in[4];
    const float* W2l = (const float*)d_in[5];
    const float* b2  = (const float*)d_in[6];
    const float* W2r = (const float*)d_in[7];
    float*       out = (float*)d_out;

    const int T = 256;
    const int grid_k1    = NB_ZERO + NB_PRE;
    const int grid_k2    = NB_EDGE + NB_PRE + NB_ZERO;
    const int grid_node4 = (N_NODES * 4 + T - 1) / T;
    const int grid_node  = (N_NODES + T - 1) / T;

    k1         <<<grid_k1,    T>>>(x, W1l);
    k2         <<<grid_k2,    T>>>(ei, x, W1r);
    k3_node1   <<<grid_node4, T>>>(b1);
    k4_scatter2<<<NB_EDGE,    T>>>(ei);
    k5_node2   <<<grid_node,  T>>>(out, W2l, b2, W2r);
}

// round 12
// speedup vs baseline: 1.2687x; 1.2687x over previous
#include <cuda_runtime.h>

#define N_NODES 100000
#define N_EDGES 1600000
#define F_IN 32
#define HID 16

// Scratch (no allocations allowed in kernel_launch)
__device__ __align__(16) float g_deg [N_NODES];
__device__ __align__(16) float g_xt  [N_NODES * HID];   // x @ W1_l.T
__device__ __align__(16) float g_xr1 [N_NODES * HID];   // x @ W1_r.T
__device__ __align__(16) float g_sum1[N_NODES * HID];   // fp32 accumulators L1
__device__ __align__(16) float g_h   [N_NODES * HID];   // relu(layer1)
__device__ __align__(16) float g_sumh[N_NODES * HID];   // fp32 accumulators L2

__device__ __forceinline__ void red_add_v4(float* addr, float4 v) {
    asm volatile("red.global.add.v4.f32 [%0], {%1,%2,%3,%4};"
                 :: "l"(addr), "f"(v.x), "f"(v.y), "f"(v.z), "f"(v.w)
                 : "memory");
}

// ---------------------------------------------------------------------------
// 1) k_pre: 1 thread/node. Zeroes sum1/sumh/deg rows; computes BOTH
//    xt = x@W1l.T and xr1 = x@W1r.T from one read of x.
//    Weight reads are LDS.128 at warp-uniform addresses (broadcast).
// ---------------------------------------------------------------------------
__global__ void __launch_bounds__(256) k_pre(const float* __restrict__ x,
                                             const float* __restrict__ W1l,
                                             const float* __restrict__ W1r) {
    __shared__ float Wl[HID * F_IN];
    __shared__ float Wr[HID * F_IN];
    for (int i = threadIdx.x; i < HID * F_IN; i += blockDim.x) {
        Wl[i] = W1l[i];
        Wr[i] = W1r[i];
    }
    __syncthreads();

    int n = blockIdx.x * blockDim.x + threadIdx.x;
    if (n >= N_NODES) return;

    g_deg[n] = 0.0f;
    float4 z = make_float4(0.f, 0.f, 0.f, 0.f);
    float4* s1 = reinterpret_cast<float4*>(g_sum1 + (size_t)n * HID);
    float4* s2 = reinterpret_cast<float4*>(g_sumh + (size_t)n * HID);
#pragma unroll
    for (int q = 0; q < HID / 4; q++) { s1[q] = z; s2[q] = z; }

    float xr[F_IN];
    const float4* xp = reinterpret_cast<const float4*>(x + (size_t)n * F_IN);
#pragma unroll
    for (int g = 0; g < F_IN / 4; g++) {
        float4 v = __ldg(xp + g);
        xr[4*g+0] = v.x; xr[4*g+1] = v.y; xr[4*g+2] = v.z; xr[4*g+3] = v.w;
    }

    const float4* Wl4 = reinterpret_cast<const float4*>(Wl);
    const float4* Wr4 = reinterpret_cast<const float4*>(Wr);

    float4* op_t = reinterpret_cast<float4*>(g_xt  + (size_t)n * HID);
    float4* op_r = reinterpret_cast<float4*>(g_xr1 + (size_t)n * HID);
#pragma unroll
    for (int og = 0; og < HID / 4; og++) {
        float4 rt, rr;
        float* rtp = &rt.x;
        float* rrp = &rr.x;
#pragma unroll
        for (int oo = 0; oo < 4; oo++) {
            int o = og * 4 + oo;
            float at = 0.0f, ar = 0.0f;
#pragma unroll
            for (int kg = 0; kg < F_IN / 4; kg++) {
                float4 wl = Wl4[o * (F_IN / 4) + kg];
                float4 wr = Wr4[o * (F_IN / 4) + kg];
                at += xr[4*kg+0] * wl.x + xr[4*kg+1] * wl.y
                    + xr[4*kg+2] * wl.z + xr[4*kg+3] * wl.w;
                ar += xr[4*kg+0] * wr.x + xr[4*kg+1] * wr.y
                    + xr[4*kg+2] * wr.z + xr[4*kg+3] * wr.w;
            }
            rtp[oo] = at;
            rrp[oo] = ar;
        }
        op_t[og] = rt;
        op_r[og] = rr;
    }
}

// ---------------------------------------------------------------------------
// 2) edge scatter layer 1: sum1[dst] += xt[src]; deg[dst] += 1  (4 thr/edge)
// ---------------------------------------------------------------------------
__global__ void k_scatter1(const int* __restrict__ ei) {
    unsigned t = blockIdx.x * blockDim.x + threadIdx.x;
    unsigned e = t >> 2;
    unsigned q = t & 3;
    if (e >= N_EDGES) return;
    int s = __ldg(ei + e);
    int d = __ldg(ei + N_EDGES + e);

    if (q == 0) atomicAdd(&g_deg[d], 1.0f);

    float4 v = *reinterpret_cast<const float4*>(g_xt + (size_t)s * HID + q * 4);
    red_add_v4(g_sum1 + (size_t)d * HID + q * 4, v);
}

// ---------------------------------------------------------------------------
// 3) h = relu(sum1/max(deg,1) + b1 + xr1)   — elementwise, 4 thr/node
// ---------------------------------------------------------------------------
__global__ void k_node1(const float* __restrict__ b1) {
    unsigned t = blockIdx.x * blockDim.x + threadIdx.x;
    unsigned n = t >> 2;
    unsigned q = t & 3;
    if (n >= N_NODES) return;

    float inv = 1.0f / fmaxf(__ldg(&g_deg[n]), 1.0f);
    float4 s = *reinterpret_cast<const float4*>(g_sum1 + (size_t)n * HID + q * 4);
    float4 r = *reinterpret_cast<const float4*>(g_xr1  + (size_t)n * HID + q * 4);
    float4 b = __ldg(reinterpret_cast<const float4*>(b1) + q);

    float4 o;
    o.x = fmaxf(s.x * inv + b.x + r.x, 0.0f);
    o.y = fmaxf(s.y * inv + b.y + r.y, 0.0f);
    o.z = fmaxf(s.z * inv + b.z + r.z, 0.0f);
    o.w = fmaxf(s.w * inv + b.w + r.w, 0.0f);
    *reinterpret_cast<float4*>(g_h + (size_t)n * HID + q * 4) = o;
}

// ---------------------------------------------------------------------------
// 4) edge scatter layer 2: sumh[dst] += h[src]  (4 threads/edge)
// ---------------------------------------------------------------------------
__global__ void k_scatter2(const int* __restrict__ ei) {
    unsigned t = blockIdx.x * blockDim.x + threadIdx.x;
    unsigned e = t >> 2;
    unsigned q = t & 3;
    if (e >= N_EDGES) return;
    int s = __ldg(ei + e);
    int d = __ldg(ei + N_EDGES + e);

    float4 v = *reinterpret_cast<const float4*>(g_h + (size_t)s * HID + q * 4);
    red_add_v4(g_sumh + (size_t)d * HID + q * 4, v);
}

// ---------------------------------------------------------------------------
// 5) k_node2: 1 thread/node, LDS.128 weight broadcasts.
//    out = (sumh*inv)@W2_l.T + b2 + h@W2_r.T
// ---------------------------------------------------------------------------
__global__ void __launch_bounds__(256) k_node2(float* __restrict__ out,
                        const float* __restrict__ W2l,
                        const float* __restrict__ b2,
                        const float* __restrict__ W2r) {
    __shared__ float Wl[F_IN * HID];
    __shared__ float Wr[F_IN * HID];
    __shared__ float bs[F_IN];
    for (int i = threadIdx.x; i < F_IN * HID; i += blockDim.x) {
        Wl[i] = W2l[i];
        Wr[i] = W2r[i];
    }
    if (threadIdx.x < F_IN) bs[threadIdx.x] = b2[threadIdx.x];
    __syncthreads();

    int n = blockIdx.x * blockDim.x + threadIdx.x;
    if (n >= N_NODES) return;

    float inv = 1.0f / fmaxf(g_deg[n], 1.0f);

    float hr[HID], ar[HID];
    const float4* hp = reinterpret_cast<const float4*>(g_h    + (size_t)n * HID);
    const float4* ap = reinterpret_cast<const float4*>(g_sumh + (size_t)n * HID);
#pragma unroll
    for (int g = 0; g < HID / 4; g++) {
        float4 v = hp[g];
        hr[4*g+0] = v.x; hr[4*g+1] = v.y; hr[4*g+2] = v.z; hr[4*g+3] = v.w;
        float4 a = ap[g];
        ar[4*g+0] = a.x * inv; ar[4*g+1] = a.y * inv;
        ar[4*g+2] = a.z * inv; ar[4*g+3] = a.w * inv;
    }

    const float4* Wl4 = reinterpret_cast<const float4*>(Wl);
    const float4* Wr4 = reinterpret_cast<const float4*>(Wr);

    float4* op = reinterpret_cast<float4*>(out + (size_t)n * F_IN);
#pragma unroll
    for (int fg = 0; fg < F_IN / 4; fg++) {
        float4 r;
        float* rp = &r.x;
#pragma unroll
        for (int ff = 0; ff < 4; ff++) {
            int f = fg * 4 + ff;
            float acc = bs[f];
#pragma unroll
            for (int kg = 0; kg < HID / 4; kg++) {
                float4 wl = Wl4[f * (HID / 4) + kg];
                float4 wr = Wr4[f * (HID / 4) + kg];
                acc += ar[4*kg+0] * wl.x + ar[4*kg+1] * wl.y
                     + ar[4*kg+2] * wl.z + ar[4*kg+3] * wl.w
                     + hr[4*kg+0] * wr.x + hr[4*kg+1] * wr.y
                     + hr[4*kg+2] * wr.z + hr[4*kg+3] * wr.w;
            }
            rp[ff] = acc;
        }
        op[fg] = r;
    }
}

// ---------------------------------------------------------------------------
extern "C" void kernel_launch(void* const* d_in, const int* in_sizes, int n_in,
                              void* d_out, int out_size) {
    const float* x   = (const float*)d_in[0];
    const int*   ei  = (const int*)d_in[1];   // [1,2,E], int32 (JAX x64 off)
    const float* W1l = (const float*)d_in[2];
    const float* b1  = (const float*)d_in[3];
    const float* W1r = (const float*)d_in[4];
    const float* W2l = (const float*)d_in[5];
    const float* b2  = (const float*)d_in[6];
    const float* W2r = (const float*)d_in[7];
    float*       out = (float*)d_out;

    const int T = 256;
    const int grid_node  = (N_NODES + T - 1) / T;
    const int grid_node4 = (N_NODES * 4 + T - 1) / T;
    const int grid_edge4 = ((N_EDGES * 4) + T - 1) / T;

    k_pre     <<<grid_node,  T>>>(x, W1l, W1r);
    k_scatter1<<<grid_edge4, T>>>(ei);
    k_node1   <<<grid_node4, T>>>(b1);
    k_scatter2<<<grid_edge4, T>>>(ei);
    k_node2   <<<grid_node,  T>>>(out, W2l, b2, W2r);
}

// round 13
// speedup vs baseline: 1.3265x; 1.0455x over previous
#include <cuda_runtime.h>

#define N_NODES 100000
#define N_EDGES 1600000
#define F_IN 32
#define HID 16

// Scratch (no allocations allowed in kernel_launch)
__device__ __align__(16) float g_deg [N_NODES];
__device__ __align__(16) float g_xt  [N_NODES * HID];   // x @ W1_l.T
__device__ __align__(16) float g_xr1 [N_NODES * HID];   // x @ W1_r.T
__device__ __align__(16) float g_sum1[N_NODES * HID];   // fp32 accumulators L1
__device__ __align__(16) float g_h   [N_NODES * HID];   // relu(layer1)
__device__ __align__(16) float g_sumh[N_NODES * HID];   // fp32 accumulators L2

__device__ __forceinline__ void red_add_v4(float* addr, float4 v) {
    asm volatile("red.global.add.v4.f32 [%0], {%1,%2,%3,%4};"
                 :: "l"(addr), "f"(v.x), "f"(v.y), "f"(v.z), "f"(v.w)
                 : "memory");
}

// ---------------------------------------------------------------------------
// 1) k_pre: 1 thread/node. Zeroes sum1/sumh/deg rows; computes BOTH
//    xt = x@W1l.T and xr1 = x@W1r.T from one read of x. LDS.128 weights.
// ---------------------------------------------------------------------------
__global__ void __launch_bounds__(256) k_pre(const float* __restrict__ x,
                                             const float* __restrict__ W1l,
                                             const float* __restrict__ W1r) {
    __shared__ float Wl[HID * F_IN];
    __shared__ float Wr[HID * F_IN];
    for (int i = threadIdx.x; i < HID * F_IN; i += blockDim.x) {
        Wl[i] = W1l[i];
        Wr[i] = W1r[i];
    }
    __syncthreads();

    int n = blockIdx.x * blockDim.x + threadIdx.x;
    if (n >= N_NODES) return;

    g_deg[n] = 0.0f;
    float4 z = make_float4(0.f, 0.f, 0.f, 0.f);
    float4* s1 = reinterpret_cast<float4*>(g_sum1 + (size_t)n * HID);
    float4* s2 = reinterpret_cast<float4*>(g_sumh + (size_t)n * HID);
#pragma unroll
    for (int q = 0; q < HID / 4; q++) { s1[q] = z; s2[q] = z; }

    float xr[F_IN];
    const float4* xp = reinterpret_cast<const float4*>(x + (size_t)n * F_IN);
#pragma unroll
    for (int g = 0; g < F_IN / 4; g++) {
        float4 v = __ldg(xp + g);
        xr[4*g+0] = v.x; xr[4*g+1] = v.y; xr[4*g+2] = v.z; xr[4*g+3] = v.w;
    }

    const float4* Wl4 = reinterpret_cast<const float4*>(Wl);
    const float4* Wr4 = reinterpret_cast<const float4*>(Wr);

    float4* op_t = reinterpret_cast<float4*>(g_xt  + (size_t)n * HID);
    float4* op_r = reinterpret_cast<float4*>(g_xr1 + (size_t)n * HID);
#pragma unroll
    for (int og = 0; og < HID / 4; og++) {
        float4 rt, rr;
        float* rtp = &rt.x;
        float* rrp = &rr.x;
#pragma unroll
        for (int oo = 0; oo < 4; oo++) {
            int o = og * 4 + oo;
            float at = 0.0f, ar = 0.0f;
#pragma unroll
            for (int kg = 0; kg < F_IN / 4; kg++) {
                float4 wl = Wl4[o * (F_IN / 4) + kg];
                float4 wr = Wr4[o * (F_IN / 4) + kg];
                at += xr[4*kg+0] * wl.x + xr[4*kg+1] * wl.y
                    + xr[4*kg+2] * wl.z + xr[4*kg+3] * wl.w;
                ar += xr[4*kg+0] * wr.x + xr[4*kg+1] * wr.y
                    + xr[4*kg+2] * wr.z + xr[4*kg+3] * wr.w;
            }
            rtp[oo] = at;
            rrp[oo] = ar;
        }
        op_t[og] = rt;
        op_r[og] = rr;
    }
}

// ---------------------------------------------------------------------------
// 2) scatter1: sum1[dst] += xt[src]; deg[dst] += 1  (4 thr/edge, PDL)
//    Index loads (input-only) happen BEFORE the grid dependency sync.
// ---------------------------------------------------------------------------
__global__ void k_scatter1(const int* __restrict__ ei) {
    unsigned t = blockIdx.x * blockDim.x + threadIdx.x;
    unsigned e = t >> 2;
    unsigned q = t & 3;
    int s = 0, d = 0;
    if (e < N_EDGES) {
        s = __ldcs(ei + e);
        d = __ldcs(ei + N_EDGES + e);
    }
    cudaGridDependencySynchronize();
    if (e >= N_EDGES) return;

    if (q == 0) atomicAdd(&g_deg[d], 1.0f);

    float4 v = *reinterpret_cast<const float4*>(g_xt + (size_t)s * HID + q * 4);
    red_add_v4(g_sum1 + (size_t)d * HID + q * 4, v);
}

// ---------------------------------------------------------------------------
// 3) node1: h = relu(sum1/max(deg,1) + b1 + xr1)  (4 thr/node, PDL)
// ---------------------------------------------------------------------------
__global__ void k_node1(const float* __restrict__ b1) {
    unsigned t = blockIdx.x * blockDim.x + threadIdx.x;
    unsigned n = t >> 2;
    unsigned q = t & 3;
    float4 b = make_float4(0.f, 0.f, 0.f, 0.f);
    if (n < N_NODES) b = __ldg(reinterpret_cast<const float4*>(b1) + q);
    cudaGridDependencySynchronize();
    if (n >= N_NODES) return;

    float inv = 1.0f / fmaxf(__ldg(&g_deg[n]), 1.0f);
    float4 s = *reinterpret_cast<const float4*>(g_sum1 + (size_t)n * HID + q * 4);
    float4 r = *reinterpret_cast<const float4*>(g_xr1  + (size_t)n * HID + q * 4);

    float4 o;
    o.x = fmaxf(s.x * inv + b.x + r.x, 0.0f);
    o.y = fmaxf(s.y * inv + b.y + r.y, 0.0f);
    o.z = fmaxf(s.z * inv + b.z + r.z, 0.0f);
    o.w = fmaxf(s.w * inv + b.w + r.w, 0.0f);
    *reinterpret_cast<float4*>(g_h + (size_t)n * HID + q * 4) = o;
}

// ---------------------------------------------------------------------------
// 4) scatter2: sumh[dst] += h[src]  (4 thr/edge, PDL)
// ---------------------------------------------------------------------------
__global__ void k_scatter2(const int* __restrict__ ei) {
    unsigned t = blockIdx.x * blockDim.x + threadIdx.x;
    unsigned e = t >> 2;
    unsigned q = t & 3;
    int s = 0, d = 0;
    if (e < N_EDGES) {
        s = __ldcs(ei + e);
        d = __ldcs(ei + N_EDGES + e);
    }
    cudaGridDependencySynchronize();
    if (e >= N_EDGES) return;

    float4 v = *reinterpret_cast<const float4*>(g_h + (size_t)s * HID + q * 4);
    red_add_v4(g_sumh + (size_t)d * HID + q * 4, v);
}

// ---------------------------------------------------------------------------
// 5) node2: out = (sumh*inv)@W2_l.T + b2 + h@W2_r.T  (1 thr/node, PDL)
//    Weight staging to smem happens BEFORE the grid dependency sync.
// ---------------------------------------------------------------------------
__global__ void __launch_bounds__(256) k_node2(float* __restrict__ out,
                        const float* __restrict__ W2l,
                        const float* __restrict__ b2,
                        const float* __restrict__ W2r) {
    __shared__ float Wl[F_IN * HID];
    __shared__ float Wr[F_IN * HID];
    __shared__ float bs[F_IN];
    for (int i = threadIdx.x; i < F_IN * HID; i += blockDim.x) {
        Wl[i] = W2l[i];
        Wr[i] = W2r[i];
    }
    if (threadIdx.x < F_IN) bs[threadIdx.x] = b2[threadIdx.x];
    __syncthreads();

    cudaGridDependencySynchronize();

    int n = blockIdx.x * blockDim.x + threadIdx.x;
    if (n >= N_NODES) return;

    float inv = 1.0f / fmaxf(g_deg[n], 1.0f);

    float hr[HID], ar[HID];
    const float4* hp = reinterpret_cast<const float4*>(g_h    + (size_t)n * HID);
    const float4* ap = reinterpret_cast<const float4*>(g_sumh + (size_t)n * HID);
#pragma unroll
    for (int g = 0; g < HID / 4; g++) {
        float4 v = hp[g];
        hr[4*g+0] = v.x; hr[4*g+1] = v.y; hr[4*g+2] = v.z; hr[4*g+3] = v.w;
        float4 a = ap[g];
        ar[4*g+0] = a.x * inv; ar[4*g+1] = a.y * inv;
        ar[4*g+2] = a.z * inv; ar[4*g+3] = a.w * inv;
    }

    const float4* Wl4 = reinterpret_cast<const float4*>(Wl);
    const float4* Wr4 = reinterpret_cast<const float4*>(Wr);

    float4* op = reinterpret_cast<float4*>(out + (size_t)n * F_IN);
#pragma unroll
    for (int fg = 0; fg < F_IN / 4; fg++) {
        float4 r;
        float* rp = &r.x;
#pragma unroll
        for (int ff = 0; ff < 4; ff++) {
            int f = fg * 4 + ff;
            float acc = bs[f];
#pragma unroll
            for (int kg = 0; kg < HID / 4; kg++) {
                float4 wl = Wl4[f * (HID / 4) + kg];
                float4 wr = Wr4[f * (HID / 4) + kg];
                acc += ar[4*kg+0] * wl.x + ar[4*kg+1] * wl.y
                     + ar[4*kg+2] * wl.z + ar[4*kg+3] * wl.w
                     + hr[4*kg+0] * wr.x + hr[4*kg+1] * wr.y
                     + hr[4*kg+2] * wr.z + hr[4*kg+3] * wr.w;
            }
            rp[ff] = acc;
        }
        op[fg] = r;
    }
}

// ---------------------------------------------------------------------------
// PDL launch helper: dependent kernel may start during predecessor's tail;
// it synchronizes via cudaGridDependencySynchronize() before consuming data.
// ---------------------------------------------------------------------------
static void launch_pdl(const void* func, int grid, int block, void** args) {
    cudaLaunchConfig_t cfg = {};
    cfg.gridDim  = dim3(grid, 1, 1);
    cfg.blockDim = dim3(block, 1, 1);
    cfg.stream = 0;
    cudaLaunchAttribute attr[1];
    attr[0].id = cudaLaunchAttributeProgrammaticStreamSerialization;
    attr[0].val.programmaticStreamSerializationAllowed = 1;
    cfg.attrs = attr;
    cfg.numAttrs = 1;
    cudaLaunchKernelExC(&cfg, func, args);
}

extern "C" void kernel_launch(void* const* d_in, const int* in_sizes, int n_in,
                              void* d_out, int out_size) {
    const float* x   = (const float*)d_in[0];
    const int*   ei  = (const int*)d_in[1];   // [1,2,E], int32 (JAX x64 off)
    const float* W1l = (const float*)d_in[2];
    const float* b1  = (const float*)d_in[3];
    const float* W1r = (const float*)d_in[4];
    const float* W2l = (const float*)d_in[5];
    const float* b2  = (const float*)d_in[6];
    const float* W2r = (const float*)d_in[7];
    float*       out = (float*)d_out;

    const int T = 256;
    const int grid_node  = (N_NODES + T - 1) / T;
    const int grid_node4 = (N_NODES * 4 + T - 1) / T;
    const int grid_edge4 = ((N_EDGES * 4) + T - 1) / T;

    k_pre<<<grid_node, T>>>(x, W1l, W1r);

    {
        void* args[] = { (void*)&ei };
        launch_pdl((const void*)k_scatter1, grid_edge4, T, args);
    }
    {
        void* args[] = { (void*)&b1 };
        launch_pdl((const void*)k_node1, grid_node4, T, args);
    }
    {
        void* args[] = { (void*)&ei };
        launch_pdl((const void*)k_scatter2, grid_edge4, T, args);
    }
    {
        void* args[] = { (void*)&out, (void*)&W2l, (void*)&b2, (void*)&W2r };
        launch_pdl((const void*)k_node2, grid_node, T, args);
    }
}